// round 16
// baseline (speedup 1.0000x reference)
#include <cuda_runtime.h>
#include <cstdint>

#define DD 16
#define NN 32
#define HH 128
#define TMROWS 448
#define THREADS 448
#define WARPS 14

// smem float-index offsets
#define OF_XT    0
#define OF_B2    16
#define OF_B1P   48
#define OF_W1    176
#define W1_STR   24                          /* [128][24] zipped */
#define OF_W2    (OF_W1 + HH*W1_STR)         /* 3248 */
#define W2_STR   136                         /* [32][136] zipped */
#define OF_F     (OF_W2 + NN*W2_STR)         /* 7600 */
#define F_STR    520                         /* [16][520] zipped */
#define OF_DIFF  (OF_F + DD*F_STR)           /* 15920 */
#define DF_STR   20                          /* [448][20] */
#define OF_H     (OF_DIFF + TMROWS*DF_STR)   /* per warp [16][68] */
#define H_STR    68
#define OF_WB    (OF_H + WARPS*16*H_STR)     /* per warp [32][36] */
#define WB_STR   36
#define SMEM_FLOATS (OF_WB + WARPS*32*WB_STR)
#define SMEM_BYTES  (SMEM_FLOATS*4)

__device__ __forceinline__ int zip8(int kk) { return ((kk & 3) << 1) | ((kk >> 2) & 1); }

__device__ __forceinline__ uint32_t tf32u(float x) {
    uint32_t u; asm("cvt.rna.tf32.f32 %0, %1;" : "=r"(u) : "f"(x)); return u;
}
__device__ __forceinline__ float tf32f(float x) {
    uint32_t u; asm("cvt.rna.tf32.f32 %0, %1;" : "=r"(u) : "f"(x)); return __uint_as_float(u);
}
__device__ __forceinline__ void mma8(float& c0, float& c1, float& c2, float& c3,
                                     uint32_t a0, uint32_t a1, uint32_t a2, uint32_t a3,
                                     uint32_t b0, uint32_t b1) {
    asm("mma.sync.aligned.m16n8k8.row.col.f32.tf32.tf32.f32 "
        "{%0,%1,%2,%3},{%4,%5,%6,%7},{%8,%9},{%0,%1,%2,%3};"
        : "+f"(c0), "+f"(c1), "+f"(c2), "+f"(c3)
        : "r"(a0), "r"(a1), "r"(a2), "r"(a3), "r"(b0), "r"(b1));
}

__global__ __launch_bounds__(THREADS, 1)
void fused_gated_ds_mma(
    const float* __restrict__ x_cur,
    const float* __restrict__ W1,
    const float* __restrict__ b1,
    const float* __restrict__ W2,
    const float* __restrict__ b2,
    const float* __restrict__ Bm,
    const float* __restrict__ Cm,
    const float* __restrict__ xt,
    float* __restrict__ out,
    int Btot, int ntiles)
{
    extern __shared__ float sm[];
    uint32_t* smu = (uint32_t*)sm;

    const int tid  = threadIdx.x;
    const int warp = tid >> 5;
    const int lane = tid & 31;
    const int g    = lane >> 2;   // groupID
    const int tig  = lane & 3;    // thread-in-group

    // ---- stage small vectors ----
    if (tid < DD) sm[OF_XT + tid] = xt[tid];
    if (tid < NN) sm[OF_B2 + tid] = b2[tid];
    __syncthreads();

    // ---- stage weights once (zipped B layouts: pair (k, k+4) adjacent) ----
    for (int i = tid; i < HH*DD; i += THREADS) {          // W1 [j][d]
        int j = i >> 4, d = i & 15;
        sm[OF_W1 + j*W1_STR + ((d >> 3) << 3) + zip8(d & 7)] = tf32f(W1[i]);
    }
    for (int i = tid; i < NN*HH; i += THREADS) {          // W2 [n][j]
        int n = i >> 7, j = i & 127;
        sm[OF_W2 + n*W2_STR + ((j >> 3) << 3) + zip8(j & 7)] = tf32f(W2[i]);
    }
    for (int i = tid; i < DD*NN*DD; i += THREADS) {       // F [k][q], q=n*16+d
        int k = i >> 9, q = i & 511;
        int n = q >> 4, d = q & 15;
        int src = n*256 + k*16 + d;
        sm[OF_F + k*F_STR + ((q >> 3) << 3) + zip8(q & 7)] = tf32f(Bm[src] + Cm[src]);
    }
    if (tid < HH) {                                        // b1'[j] = b1[j] + W1 xt
        float s = b1[tid];
        #pragma unroll
        for (int d = 0; d < DD; d++) s += W1[tid*DD + d] * sm[OF_XT + d];
        sm[OF_B1P + tid] = s;
    }
    __syncthreads();

    const int wrb = warp * 32;                  // 32 rows per warp now
    float* sD  = sm + OF_DIFF + wrb*DF_STR;     // this warp's 32-row diff slice
    float* sH  = sm + OF_H  + warp*16*H_STR;    // 16-row scratch (per subtile)
    float* sWb = sm + OF_WB + warp*32*WB_STR;   // 32-row softmax weights
    uint32_t* sHu = (uint32_t*)sH;

    // no CTA barriers below: each warp owns its diff/H/WB slices
    for (int tile = blockIdx.x; tile < ntiles; tile += gridDim.x) {
        // ---- per-warp diff staging: lane r covers one full row (16 floats) ----
        {
            const int row = tile*TMROWS + wrb + lane;
            float4 d0 = make_float4(0.f,0.f,0.f,0.f), d1 = d0, d2 = d0, d3 = d0;
            if (row < Btot) {
                const float4* xg = (const float4*)(x_cur + (size_t)row*DD);
                float4 v0 = xg[0], v1 = xg[1], v2 = xg[2], v3 = xg[3];
                d0.x = sm[OF_XT+0]  - v0.x; d0.y = sm[OF_XT+1]  - v0.y;
                d0.z = sm[OF_XT+2]  - v0.z; d0.w = sm[OF_XT+3]  - v0.w;
                d1.x = sm[OF_XT+4]  - v1.x; d1.y = sm[OF_XT+5]  - v1.y;
                d1.z = sm[OF_XT+6]  - v1.z; d1.w = sm[OF_XT+7]  - v1.w;
                d2.x = sm[OF_XT+8]  - v2.x; d2.y = sm[OF_XT+9]  - v2.y;
                d2.z = sm[OF_XT+10] - v2.z; d2.w = sm[OF_XT+11] - v2.w;
                d3.x = sm[OF_XT+12] - v3.x; d3.y = sm[OF_XT+13] - v3.y;
                d3.z = sm[OF_XT+14] - v3.z; d3.w = sm[OF_XT+15] - v3.w;
            }
            *(float4*)(sD + lane*DF_STR + 0)  = d0;
            *(float4*)(sD + lane*DF_STR + 4)  = d1;
            *(float4*)(sD + lane*DF_STR + 8)  = d2;
            *(float4*)(sD + lane*DF_STR + 12) = d3;
        }
        __syncwarp();

        // ======== per-subtile: G1 (interleaved halves) + G2 + softmax ========
        #pragma unroll 1
        for (int s = 0; s < 2; s++) {
            float* sDs  = sD  + s*16*DF_STR;
            float* sWbS = sWb + s*16*WB_STR;

            uint32_t af[2][4];
            #pragma unroll
            for (int ks = 0; ks < 2; ks++) {
                af[ks][0] = tf32u(sDs[(g  )*DF_STR + ks*8 + tig    ]);
                af[ks][1] = tf32u(sDs[(g+8)*DF_STR + ks*8 + tig    ]);
                af[ks][2] = tf32u(sDs[(g  )*DF_STR + ks*8 + tig + 4]);
                af[ks][3] = tf32u(sDs[(g+8)*DF_STR + ks*8 + tig + 4]);
            }

            float acc2[4][4];
            #pragma unroll
            for (int nt = 0; nt < 4; nt++)
                acc2[nt][0] = acc2[nt][1] = acc2[nt][2] = acc2[nt][3] = 0.f;

            #pragma unroll
            for (int half = 0; half < 2; half++) {
                float acc1h[8][4];
                #pragma unroll
                for (int ntl = 0; ntl < 8; ntl++)
                    acc1h[ntl][0] = acc1h[ntl][1] = acc1h[ntl][2] = acc1h[ntl][3] = 0.f;
                #pragma unroll
                for (int ks = 0; ks < 2; ks++) {
                    #pragma unroll
                    for (int ntl = 0; ntl < 8; ntl++) {
                        const int nt = half*8 + ntl;
                        uint2 bv = *(uint2*)(smu + OF_W1 + (nt*8+g)*W1_STR + ks*8 + 2*tig);
                        mma8(acc1h[ntl][0], acc1h[ntl][1], acc1h[ntl][2], acc1h[ntl][3],
                             af[ks][0], af[ks][1], af[ks][2], af[ks][3], bv.x, bv.y);
                    }
                }

                #pragma unroll
                for (int ntl = 0; ntl < 8; ntl++) {
                    const int nt = half*8 + ntl;
                    const int c0 = nt*8 + 2*tig;
                    const int cl = ntl*8 + 2*tig;
                    float2 bb = *(float2*)(sm + OF_B1P + c0);
                    float2 h0, h1;
                    h0.x = tf32f(fmaxf(bb.x - acc1h[ntl][0], 0.f));
                    h0.y = tf32f(fmaxf(bb.y - acc1h[ntl][1], 0.f));
                    h1.x = tf32f(fmaxf(bb.x - acc1h[ntl][2], 0.f));
                    h1.y = tf32f(fmaxf(bb.y - acc1h[ntl][3], 0.f));
                    *(float2*)(sH + (g  )*H_STR + cl) = h0;
                    *(float2*)(sH + (g+8)*H_STR + cl) = h1;
                }
                __syncwarp();

                #pragma unroll
                for (int ktl = 0; ktl < 8; ktl++) {
                    const int kt = half*8 + ktl;
                    uint32_t a0 = sHu[(g  )*H_STR + ktl*8 + tig];
                    uint32_t a1 = sHu[(g+8)*H_STR + ktl*8 + tig];
                    uint32_t a2 = sHu[(g  )*H_STR + ktl*8 + tig + 4];
                    uint32_t a3 = sHu[(g+8)*H_STR + ktl*8 + tig + 4];
                    #pragma unroll
                    for (int nt = 0; nt < 4; nt++) {
                        uint2 bv = *(uint2*)(smu + OF_W2 + (nt*8+g)*W2_STR + kt*8 + 2*tig);
                        mma8(acc2[nt][0], acc2[nt][1], acc2[nt][2], acc2[nt][3],
                             a0, a1, a2, a3, bv.x, bv.y);
                    }
                }
                __syncwarp();
            }

            // softmax (rows g, g+8 of this subtile)
            {
                float l0[8], l1[8];
                #pragma unroll
                for (int nt = 0; nt < 4; nt++) {
                    float2 bv = *(float2*)(sm + OF_B2 + nt*8 + 2*tig);
                    l0[2*nt]   = acc2[nt][0] + bv.x;  l0[2*nt+1] = acc2[nt][1] + bv.y;
                    l1[2*nt]   = acc2[nt][2] + bv.x;  l1[2*nt+1] = acc2[nt][3] + bv.y;
                }
                float m0 = l0[0], m1 = l1[0];
                #pragma unroll
                for (int i = 1; i < 8; i++) { m0 = fmaxf(m0, l0[i]); m1 = fmaxf(m1, l1[i]); }
                m0 = fmaxf(m0, __shfl_xor_sync(0xffffffffu, m0, 1));
                m0 = fmaxf(m0, __shfl_xor_sync(0xffffffffu, m0, 2));
                m1 = fmaxf(m1, __shfl_xor_sync(0xffffffffu, m1, 1));
                m1 = fmaxf(m1, __shfl_xor_sync(0xffffffffu, m1, 2));
                float s0 = 0.f, s1 = 0.f;
                #pragma unroll
                for (int i = 0; i < 8; i++) {
                    l0[i] = __expf(l0[i] - m0); s0 += l0[i];
                    l1[i] = __expf(l1[i] - m1); s1 += l1[i];
                }
                s0 += __shfl_xor_sync(0xffffffffu, s0, 1);
                s0 += __shfl_xor_sync(0xffffffffu, s0, 2);
                s1 += __shfl_xor_sync(0xffffffffu, s1, 1);
                s1 += __shfl_xor_sync(0xffffffffu, s1, 2);
                const float i0 = 1.f / s0, i1 = 1.f / s1;
                #pragma unroll
                for (int nt = 0; nt < 4; nt++) {
                    float2 w0 = make_float2(l0[2*nt]*i0, l0[2*nt+1]*i0);
                    float2 w1 = make_float2(l1[2*nt]*i1, l1[2*nt+1]*i1);
                    *(float2*)(sWbS + (g  )*WB_STR + nt*8 + 2*tig) = w0;
                    *(float2*)(sWbS + (g+8)*WB_STR + nt*8 + 2*tig) = w1;
                }
            }
            __syncwarp();
        }

        // ===== G3 with M=32: each F-fragment load serves BOTH subtiles =====
        float dg[2][2][4];   // [subtile][rowhalf][k4]
        #pragma unroll
        for (int s = 0; s < 2; s++)
            #pragma unroll
            for (int k4 = 0; k4 < 4; k4++) {
                dg[s][0][k4] = sD[(s*16+g  )*DF_STR + k4*4 + tig];
                dg[s][1][k4] = sD[(s*16+g+8)*DF_STR + k4*4 + tig];
            }
        float acc3[2][2][4]; // [subtile][nt][c]
        #pragma unroll
        for (int s = 0; s < 2; s++)
            #pragma unroll
            for (int nt = 0; nt < 2; nt++)
                acc3[s][nt][0] = acc3[s][nt][1] = acc3[s][nt][2] = acc3[s][nt][3] = 0.f;

        #pragma unroll 2
        for (int ktp = 0; ktp < 32; ktp++) {       // n = ktp
            float wgv[2][2];
            #pragma unroll
            for (int s = 0; s < 2; s++) {
                wgv[s][0] = sWb[(s*16+g  )*WB_STR + ktp];
                wgv[s][1] = sWb[(s*16+g+8)*WB_STR + ktp];
            }
            const int kb = ktp * 16;
            // kt even (d = tig, tig+4)
            {
                uint2 bv0 = *(uint2*)(smu + OF_F + (g  )*F_STR + kb + 2*tig);
                uint2 bv1 = *(uint2*)(smu + OF_F + (8+g)*F_STR + kb + 2*tig);
                #pragma unroll
                for (int s = 0; s < 2; s++) {
                    uint32_t a0 = tf32u(wgv[s][0] * dg[s][0][0]);
                    uint32_t a1 = tf32u(wgv[s][1] * dg[s][1][0]);
                    uint32_t a2 = tf32u(wgv[s][0] * dg[s][0][1]);
                    uint32_t a3 = tf32u(wgv[s][1] * dg[s][1][1]);
                    mma8(acc3[s][0][0], acc3[s][0][1], acc3[s][0][2], acc3[s][0][3],
                         a0, a1, a2, a3, bv0.x, bv0.y);
                    mma8(acc3[s][1][0], acc3[s][1][1], acc3[s][1][2], acc3[s][1][3],
                         a0, a1, a2, a3, bv1.x, bv1.y);
                }
            }
            // kt odd (d = tig+8, tig+12)
            {
                uint2 bv0 = *(uint2*)(smu + OF_F + (g  )*F_STR + kb + 8 + 2*tig);
                uint2 bv1 = *(uint2*)(smu + OF_F + (8+g)*F_STR + kb + 8 + 2*tig);
                #pragma unroll
                for (int s = 0; s < 2; s++) {
                    uint32_t a0 = tf32u(wgv[s][0] * dg[s][0][2]);
                    uint32_t a1 = tf32u(wgv[s][1] * dg[s][1][2]);
                    uint32_t a2 = tf32u(wgv[s][0] * dg[s][0][3]);
                    uint32_t a3 = tf32u(wgv[s][1] * dg[s][1][3]);
                    mma8(acc3[s][0][0], acc3[s][0][1], acc3[s][0][2], acc3[s][0][3],
                         a0, a1, a2, a3, bv0.x, bv0.y);
                    mma8(acc3[s][1][0], acc3[s][1][1], acc3[s][1][2], acc3[s][1][3],
                         a0, a1, a2, a3, bv1.x, bv1.y);
                }
            }
        }

        // ---- store both subtiles ----
        #pragma unroll
        for (int s = 0; s < 2; s++) {
            const int row0 = tile*TMROWS + wrb + s*16 + g;
            if (row0 < Btot) {
                *(float2*)(out + (size_t)row0*DD + 2*tig)     = make_float2(acc3[s][0][0], acc3[s][0][1]);
                *(float2*)(out + (size_t)row0*DD + 8 + 2*tig) = make_float2(acc3[s][1][0], acc3[s][1][1]);
            }
            const int row1 = row0 + 8;
            if (row1 < Btot) {
                *(float2*)(out + (size_t)row1*DD + 2*tig)     = make_float2(acc3[s][0][2], acc3[s][0][3]);
                *(float2*)(out + (size_t)row1*DD + 8 + 2*tig) = make_float2(acc3[s][1][2], acc3[s][1][3]);
            }
        }
        __syncwarp();   // protect own diff slice before next iteration
    }
}

extern "C" void kernel_launch(void* const* d_in, const int* in_sizes, int n_in,
                              void* d_out, int out_size)
{
    const float* x_cur = (const float*)d_in[0];
    const float* W1    = (const float*)d_in[1];
    const float* b1    = (const float*)d_in[2];
    const float* W2    = (const float*)d_in[3];
    const float* b2    = (const float*)d_in[4];
    const float* Bm    = (const float*)d_in[5];
    const float* Cm    = (const float*)d_in[6];
    const float* xt    = (const float*)d_in[7];
    float* out = (float*)d_out;

    const int Btot   = in_sizes[0] / DD;
    const int ntiles = (Btot + TMROWS - 1) / TMROWS;

    cudaFuncSetAttribute(fused_gated_ds_mma,
                         cudaFuncAttributeMaxDynamicSharedMemorySize, SMEM_BYTES);

    int dev = 0, sms = 148;
    cudaGetDevice(&dev);
    cudaDeviceGetAttribute(&sms, cudaDevAttrMultiProcessorCount, dev);
    const int grid = sms < ntiles ? sms : ntiles;

    fused_gated_ds_mma<<<grid, THREADS, SMEM_BYTES>>>(
        x_cur, W1, b1, W2, b2, Bm, Cm, xt, out, Btot, ntiles);
}

// round 17
// speedup vs baseline: 1.1438x; 1.1438x over previous
#include <cuda_runtime.h>
#include <cstdint>

#define DD 16
#define NN 32
#define HH 128
#define TMROWS 288
#define THREADS 576
#define WARPS 18

// smem float-index offsets
#define OF_XT    0
#define OF_B2    16
#define OF_B1P   48
#define OF_W1    176
#define W1_STR   24                          /* [128][24] zipped */
#define OF_W2    (OF_W1 + HH*W1_STR)         /* 3248 */
#define W2_STR   136                         /* [32][136] zipped */
#define OF_F     (OF_W2 + NN*W2_STR)         /* 7600 */
#define F_STR    520                         /* [16][520] zipped */
#define OF_DIFF  (OF_F + DD*F_STR)           /* 15920 */
#define DF_STR   20                          /* [288][20] */
#define OF_H     (OF_DIFF + TMROWS*DF_STR)   /* per warp [16][68] */
#define H_STR    68
#define OF_WB    (OF_H + WARPS*16*H_STR)     /* per warp [16][36] */
#define WB_STR   36
#define SMEM_FLOATS (OF_WB + WARPS*16*WB_STR)
#define SMEM_BYTES  (SMEM_FLOATS*4)

__device__ __forceinline__ int zip8(int kk) { return ((kk & 3) << 1) | ((kk >> 2) & 1); }

__device__ __forceinline__ float tf32f(float x) {
    uint32_t u; asm("cvt.rna.tf32.f32 %0, %1;" : "=r"(u) : "f"(x)); return __uint_as_float(u);
}
__device__ __forceinline__ void mma8(float& c0, float& c1, float& c2, float& c3,
                                     uint32_t a0, uint32_t a1, uint32_t a2, uint32_t a3,
                                     uint32_t b0, uint32_t b1) {
    asm("mma.sync.aligned.m16n8k8.row.col.f32.tf32.tf32.f32 "
        "{%0,%1,%2,%3},{%4,%5,%6,%7},{%8,%9},{%0,%1,%2,%3};"
        : "+f"(c0), "+f"(c1), "+f"(c2), "+f"(c3)
        : "r"(a0), "r"(a1), "r"(a2), "r"(a3), "r"(b0), "r"(b1));
}

__global__ __launch_bounds__(THREADS, 1)
void fused_gated_ds_mma(
    const float* __restrict__ x_cur,
    const float* __restrict__ W1,
    const float* __restrict__ b1,
    const float* __restrict__ W2,
    const float* __restrict__ b2,
    const float* __restrict__ Bm,
    const float* __restrict__ Cm,
    const float* __restrict__ xt,
    float* __restrict__ out,
    int Btot, int ntiles)
{
    extern __shared__ float sm[];
    uint32_t* smu = (uint32_t*)sm;

    const int tid  = threadIdx.x;
    const int warp = tid >> 5;
    const int lane = tid & 31;
    const int g    = lane >> 2;   // groupID
    const int tig  = lane & 3;    // thread-in-group

    // ---- stage small vectors ----
    if (tid < DD) sm[OF_XT + tid] = xt[tid];
    if (tid < NN) sm[OF_B2 + tid] = b2[tid];
    __syncthreads();

    // ---- stage weights once (zipped B layouts: pair (k, k+4) adjacent) ----
    for (int i = tid; i < HH*DD; i += THREADS) {          // W1 [j][d]
        int j = i >> 4, d = i & 15;
        sm[OF_W1 + j*W1_STR + ((d >> 3) << 3) + zip8(d & 7)] = tf32f(W1[i]);
    }
    for (int i = tid; i < NN*HH; i += THREADS) {          // W2 [n][j]
        int n = i >> 7, j = i & 127;
        sm[OF_W2 + n*W2_STR + ((j >> 3) << 3) + zip8(j & 7)] = tf32f(W2[i]);
    }
    for (int i = tid; i < DD*NN*DD; i += THREADS) {       // F [k][q], q=n*16+d
        int k = i >> 9, q = i & 511;
        int n = q >> 4, d = q & 15;
        int src = n*256 + k*16 + d;
        sm[OF_F + k*F_STR + ((q >> 3) << 3) + zip8(q & 7)] = tf32f(Bm[src] + Cm[src]);
    }
    if (tid < HH) {                                        // b1'[j] = b1[j] + W1 xt
        float s = b1[tid];
        #pragma unroll
        for (int d = 0; d < DD; d++) s += W1[tid*DD + d] * sm[OF_XT + d];
        sm[OF_B1P + tid] = s;
    }
    __syncthreads();

    const int wrb = warp * 16;
    float* sD  = sm + OF_DIFF + wrb*DF_STR;     // this warp's 16-row diff slice
    uint32_t* sDu = (uint32_t*)sD;
    float* sH  = sm + OF_H  + warp*16*H_STR;
    float* sWb = sm + OF_WB + warp*16*WB_STR;
    uint32_t* sHu = (uint32_t*)sH;

    // no CTA barriers below: each warp owns its diff/H/WB slices
    for (int tile = blockIdx.x; tile < ntiles; tile += gridDim.x) {
        // ---- per-warp diff staging (tf32-pre-rounded): row = lane>>1, half = lane&1 ----
        {
            const int r  = lane >> 1;
            const int h8 = (lane & 1) * 8;
            const int row = tile*TMROWS + wrb + r;
            float4 d0 = make_float4(0.f,0.f,0.f,0.f), d1 = d0;
            if (row < Btot) {
                const float4* xg = (const float4*)(x_cur + (size_t)row*DD + h8);
                float4 v0 = xg[0], v1 = xg[1];
                d0.x = tf32f(sm[OF_XT+h8+0] - v0.x); d0.y = tf32f(sm[OF_XT+h8+1] - v0.y);
                d0.z = tf32f(sm[OF_XT+h8+2] - v0.z); d0.w = tf32f(sm[OF_XT+h8+3] - v0.w);
                d1.x = tf32f(sm[OF_XT+h8+4] - v1.x); d1.y = tf32f(sm[OF_XT+h8+5] - v1.y);
                d1.z = tf32f(sm[OF_XT+h8+6] - v1.z); d1.w = tf32f(sm[OF_XT+h8+7] - v1.w);
            }
            *(float4*)(sD + r*DF_STR + h8)     = d0;
            *(float4*)(sD + r*DF_STR + h8 + 4) = d1;
        }
        __syncwarp();

        // ---- G1 A-fragments: plain uint loads (diff already tf32) ----
        uint32_t af[2][4];
        #pragma unroll
        for (int ks = 0; ks < 2; ks++) {
            af[ks][0] = sDu[(g  )*DF_STR + ks*8 + tig    ];
            af[ks][1] = sDu[(g+8)*DF_STR + ks*8 + tig    ];
            af[ks][2] = sDu[(g  )*DF_STR + ks*8 + tig + 4];
            af[ks][3] = sDu[(g+8)*DF_STR + ks*8 + tig + 4];
        }

        float acc2[4][4];
        #pragma unroll
        for (int nt = 0; nt < 4; nt++)
            acc2[nt][0] = acc2[nt][1] = acc2[nt][2] = acc2[nt][3] = 0.f;

        // ======== interleaved G1/G2 per K-half ========
        #pragma unroll
        for (int half = 0; half < 2; half++) {
            float acc1h[8][4];
            #pragma unroll
            for (int ntl = 0; ntl < 8; ntl++)
                acc1h[ntl][0] = acc1h[ntl][1] = acc1h[ntl][2] = acc1h[ntl][3] = 0.f;
            #pragma unroll
            for (int ks = 0; ks < 2; ks++) {
                #pragma unroll
                for (int ntl = 0; ntl < 8; ntl++) {
                    const int nt = half*8 + ntl;
                    uint2 bv = *(uint2*)(smu + OF_W1 + (nt*8+g)*W1_STR + ks*8 + 2*tig);
                    mma8(acc1h[ntl][0], acc1h[ntl][1], acc1h[ntl][2], acc1h[ntl][3],
                         af[ks][0], af[ks][1], af[ks][2], af[ks][3], bv.x, bv.y);
                }
            }

            // H = relu(b1' - D1) -> per-warp smem (tf32)
            #pragma unroll
            for (int ntl = 0; ntl < 8; ntl++) {
                const int nt = half*8 + ntl;
                const int c0 = nt*8 + 2*tig;
                const int cl = ntl*8 + 2*tig;
                float2 bb = *(float2*)(sm + OF_B1P + c0);
                float2 h0, h1;
                h0.x = tf32f(fmaxf(bb.x - acc1h[ntl][0], 0.f));
                h0.y = tf32f(fmaxf(bb.y - acc1h[ntl][1], 0.f));
                h1.x = tf32f(fmaxf(bb.x - acc1h[ntl][2], 0.f));
                h1.y = tf32f(fmaxf(bb.y - acc1h[ntl][3], 0.f));
                *(float2*)(sH + (g  )*H_STR + cl) = h0;
                *(float2*)(sH + (g+8)*H_STR + cl) = h1;
            }
            __syncwarp();

            #pragma unroll
            for (int ktl = 0; ktl < 8; ktl++) {
                const int kt = half*8 + ktl;
                uint32_t a0 = sHu[(g  )*H_STR + ktl*8 + tig];
                uint32_t a1 = sHu[(g+8)*H_STR + ktl*8 + tig];
                uint32_t a2 = sHu[(g  )*H_STR + ktl*8 + tig + 4];
                uint32_t a3 = sHu[(g+8)*H_STR + ktl*8 + tig + 4];
                #pragma unroll
                for (int nt = 0; nt < 4; nt++) {
                    uint2 bv = *(uint2*)(smu + OF_W2 + (nt*8+g)*W2_STR + kt*8 + 2*tig);
                    mma8(acc2[nt][0], acc2[nt][1], acc2[nt][2], acc2[nt][3],
                         a0, a1, a2, a3, bv.x, bv.y);
                }
            }
            __syncwarp();
        }

        // ---- softmax (rows g, g+8; logits of a row live in one quad) ----
        {
            float l0[8], l1[8];
            #pragma unroll
            for (int nt = 0; nt < 4; nt++) {
                float2 bv = *(float2*)(sm + OF_B2 + nt*8 + 2*tig);
                l0[2*nt]   = acc2[nt][0] + bv.x;  l0[2*nt+1] = acc2[nt][1] + bv.y;
                l1[2*nt]   = acc2[nt][2] + bv.x;  l1[2*nt+1] = acc2[nt][3] + bv.y;
            }
            float m0 = l0[0], m1 = l1[0];
            #pragma unroll
            for (int i = 1; i < 8; i++) { m0 = fmaxf(m0, l0[i]); m1 = fmaxf(m1, l1[i]); }
            m0 = fmaxf(m0, __shfl_xor_sync(0xffffffffu, m0, 1));
            m0 = fmaxf(m0, __shfl_xor_sync(0xffffffffu, m0, 2));
            m1 = fmaxf(m1, __shfl_xor_sync(0xffffffffu, m1, 1));
            m1 = fmaxf(m1, __shfl_xor_sync(0xffffffffu, m1, 2));
            float s0 = 0.f, s1 = 0.f;
            #pragma unroll
            for (int i = 0; i < 8; i++) {
                l0[i] = __expf(l0[i] - m0); s0 += l0[i];
                l1[i] = __expf(l1[i] - m1); s1 += l1[i];
            }
            s0 += __shfl_xor_sync(0xffffffffu, s0, 1);
            s0 += __shfl_xor_sync(0xffffffffu, s0, 2);
            s1 += __shfl_xor_sync(0xffffffffu, s1, 1);
            s1 += __shfl_xor_sync(0xffffffffu, s1, 2);
            const float i0 = 1.f / s0, i1 = 1.f / s1;
            #pragma unroll
            for (int nt = 0; nt < 4; nt++) {
                float2 w0 = make_float2(l0[2*nt]*i0, l0[2*nt+1]*i0);
                float2 w1 = make_float2(l1[2*nt]*i1, l1[2*nt+1]*i1);
                *(float2*)(sWb + (g  )*WB_STR + nt*8 + 2*tig) = w0;
                *(float2*)(sWb + (g+8)*WB_STR + nt*8 + 2*tig) = w1;
            }
        }
        __syncwarp();

        // ================= G3: out[16x16] = Y[16x512] @ F^T =================
        // Y fragments = raw f32 products (implicit tf32 truncation by MMA) — no cvt.
        float dgA[4], dgB[4];
        #pragma unroll
        for (int k4 = 0; k4 < 4; k4++) {
            dgA[k4] = sD[(g  )*DF_STR + k4*4 + tig];
            dgB[k4] = sD[(g+8)*DF_STR + k4*4 + tig];
        }
        float acc3[2][4];
        #pragma unroll
        for (int nt = 0; nt < 2; nt++)
            acc3[nt][0] = acc3[nt][1] = acc3[nt][2] = acc3[nt][3] = 0.f;

        #pragma unroll 4
        for (int ktp = 0; ktp < 32; ktp++) {       // n = ktp
            const float wg  = sWb[(g  )*WB_STR + ktp];
            const float wg8 = sWb[(g+8)*WB_STR + ktp];
            const int kb = ktp * 16;
            {
                uint32_t a0 = __float_as_uint(wg  * dgA[0]);
                uint32_t a1 = __float_as_uint(wg8 * dgB[0]);
                uint32_t a2 = __float_as_uint(wg  * dgA[1]);
                uint32_t a3 = __float_as_uint(wg8 * dgB[1]);
                #pragma unroll
                for (int nt = 0; nt < 2; nt++) {
                    uint2 bv = *(uint2*)(smu + OF_F + (nt*8+g)*F_STR + kb + 2*tig);
                    mma8(acc3[nt][0], acc3[nt][1], acc3[nt][2], acc3[nt][3],
                         a0, a1, a2, a3, bv.x, bv.y);
                }
            }
            {
                uint32_t a0 = __float_as_uint(wg  * dgA[2]);
                uint32_t a1 = __float_as_uint(wg8 * dgB[2]);
                uint32_t a2 = __float_as_uint(wg  * dgA[3]);
                uint32_t a3 = __float_as_uint(wg8 * dgB[3]);
                #pragma unroll
                for (int nt = 0; nt < 2; nt++) {
                    uint2 bv = *(uint2*)(smu + OF_F + (nt*8+g)*F_STR + kb + 8 + 2*tig);
                    mma8(acc3[nt][0], acc3[nt][1], acc3[nt][2], acc3[nt][3],
                         a0, a1, a2, a3, bv.x, bv.y);
                }
            }
        }

        // ---- store ----
        {
            const int row0 = tile*TMROWS + wrb + g;
            if (row0 < Btot) {
                *(float2*)(out + (size_t)row0*DD + 2*tig)     = make_float2(acc3[0][0], acc3[0][1]);
                *(float2*)(out + (size_t)row0*DD + 8 + 2*tig) = make_float2(acc3[1][0], acc3[1][1]);
            }
            const int row1 = row0 + 8;
            if (row1 < Btot) {
                *(float2*)(out + (size_t)row1*DD + 2*tig)     = make_float2(acc3[0][2], acc3[0][3]);
                *(float2*)(out + (size_t)row1*DD + 8 + 2*tig) = make_float2(acc3[1][2], acc3[1][3]);
            }
        }
        __syncwarp();   // protect own diff slice before next iteration
    }
}

extern "C" void kernel_launch(void* const* d_in, const int* in_sizes, int n_in,
                              void* d_out, int out_size)
{
    const float* x_cur = (const float*)d_in[0];
    const float* W1    = (const float*)d_in[1];
    const float* b1    = (const float*)d_in[2];
    const float* W2    = (const float*)d_in[3];
    const float* b2    = (const float*)d_in[4];
    const float* Bm    = (const float*)d_in[5];
    const float* Cm    = (const float*)d_in[6];
    const float* xt    = (const float*)d_in[7];
    float* out = (float*)d_out;

    const int Btot   = in_sizes[0] / DD;
    const int ntiles = (Btot + TMROWS - 1) / TMROWS;

    cudaFuncSetAttribute(fused_gated_ds_mma,
                         cudaFuncAttributeMaxDynamicSharedMemorySize, SMEM_BYTES);

    int dev = 0, sms = 148;
    cudaGetDevice(&dev);
    cudaDeviceGetAttribute(&sms, cudaDevAttrMultiProcessorCount, dev);
    const int grid = sms < ntiles ? sms : ntiles;

    fused_gated_ds_mma<<<grid, THREADS, SMEM_BYTES>>>(
        x_cur, W1, b1, W2, b2, Bm, Cm, xt, out, Btot, ntiles);
}